// round 6
// baseline (speedup 1.0000x reference)
#include <cuda_runtime.h>
#include <stdint.h>

#define BETA      0.99f
#define T50       50
#define B_DIM     8192
#define IN_DIM    512
#define OUT_DIM   256

#define TILE_M    64
#define TILE_N    32
#define BK        16
#define ROW_ELEMS (OUT_DIM * T50)

typedef unsigned long long ull;

__device__ __forceinline__ ull dup_f32(float f) {
    unsigned int u = __float_as_uint(f);
    return (ull)u | ((ull)u << 32);
}
__device__ __forceinline__ void fma_f32x2(ull& d, ull a, ull b) {
    asm("fma.rn.f32x2 %0, %1, %2, %0;" : "+l"(d) : "l"(a), "l"(b));
}

__global__ __launch_bounds__(128, 6) void snn_fused3(
    const float* __restrict__ x,     // [B_DIM, IN_DIM]
    const float* __restrict__ W,     // [OUT_DIM, IN_DIM]
    const float* __restrict__ bias,  // [OUT_DIM]
    float* __restrict__ out)         // [B_DIM, OUT_DIM, T50]
{
    __shared__ float As[BK][68];                 // k-major, rows contiguous (M-packed pairs)
    __shared__ ull   Bs2[BK][34];                // duplicated (b,b) per col
    __shared__ uint32_t s_msk[TILE_M * 16 * 4];  // 16 KB: [row][colpair][4 words]
    __shared__ float4 lut4[16];                  // nibble -> 4 spike floats

    const int tid  = threadIdx.x;
    const int tx   = tid & 7;            // col group (4 cols)
    const int ty   = tid >> 3;           // row group (4 rows)
    const int col0 = blockIdx.x * TILE_N;
    const int row0 = blockIdx.y * TILE_M;

    if (tid < 16)                        // one-time LUT init (synced by first barrier)
        lut4[tid] = make_float4((float)(tid & 1), (float)((tid >> 1) & 1),
                                (float)((tid >> 2) & 1), (float)((tid >> 3) & 1));

    // ---------------- GEMM: cur = x @ W^T + b  (k strictly ascending) -------
    ull acc64[8];                        // [rowpair(2)][col(4)]; halves = (row even, row odd)
#pragma unroll
    for (int e = 0; e < 8; e++) acc64[e] = 0ull;

    const int lr = tid >> 2;             // 0..31
    const int lc = (tid & 3) << 2;       // 0,4,8,12
    const float* xp0 = x + (size_t)(row0 + lr) * IN_DIM + lc;
    const float* xp1 = xp0 + (size_t)32 * IN_DIM;
    const float* wp0 = W + (size_t)(col0 + lr) * IN_DIM + lc;

    float4 va0 = *reinterpret_cast<const float4*>(xp0);
    float4 va1 = *reinterpret_cast<const float4*>(xp1);
    float4 vb0 = *reinterpret_cast<const float4*>(wp0);

    for (int k0 = 0; k0 < IN_DIM; k0 += BK) {
        As[lc + 0][lr]      = va0.x; As[lc + 1][lr]      = va0.y;
        As[lc + 2][lr]      = va0.z; As[lc + 3][lr]      = va0.w;
        As[lc + 0][lr + 32] = va1.x; As[lc + 1][lr + 32] = va1.y;
        As[lc + 2][lr + 32] = va1.z; As[lc + 3][lr + 32] = va1.w;
        Bs2[lc + 0][lr] = dup_f32(vb0.x);
        Bs2[lc + 1][lr] = dup_f32(vb0.y);
        Bs2[lc + 2][lr] = dup_f32(vb0.z);
        Bs2[lc + 3][lr] = dup_f32(vb0.w);
        __syncthreads();

        if (k0 + BK < IN_DIM) {
            va0 = *reinterpret_cast<const float4*>(xp0 + k0 + BK);
            va1 = *reinterpret_cast<const float4*>(xp1 + k0 + BK);
            vb0 = *reinterpret_cast<const float4*>(wp0 + k0 + BK);
        }

#pragma unroll
        for (int kk = 0; kk < BK; kk++) {
            ulonglong2 av = *reinterpret_cast<const ulonglong2*>(&As[kk][ty << 2]);
#pragma unroll
            for (int j = 0; j < 4; j++) {
                ull bj = Bs2[kk][(tx << 2) + j];
                fma_f32x2(acc64[j],     av.x, bj);   // rows 0,1
                fma_f32x2(acc64[4 + j], av.y, bj);   // rows 2,3
            }
        }
        __syncthreads();
    }

    float4 b4 = *reinterpret_cast<const float4*>(&bias[col0 + (tx << 2)]);
    const float bb[4] = {b4.x, b4.y, b4.z, b4.w};

    // ---------------- LIF recurrence (per row) + packed mask write ----------
#pragma unroll
    for (int i = 0; i < 4; i++) {
        // currents for row i, cols 0..3 (bit-exact: plain fp32 add of bias)
        float c0, c1, c2, c3;
        {
            const int p = (i >> 1) << 2;   // rowpair base in acc64
            const int h = i & 1;           // which half
            float2 v0 = reinterpret_cast<float2*>(&acc64[p + 0])[0];
            float2 v1 = reinterpret_cast<float2*>(&acc64[p + 1])[0];
            float2 v2 = reinterpret_cast<float2*>(&acc64[p + 2])[0];
            float2 v3 = reinterpret_cast<float2*>(&acc64[p + 3])[0];
            c0 = (h ? v0.y : v0.x) + bb[0];
            c1 = (h ? v1.y : v1.x) + bb[1];
            c2 = (h ? v2.y : v2.x) + bb[2];
            c3 = (h ? v3.y : v3.x) + bb[3];
        }

        float m0 = 0.f, m1 = 0.f, m2 = 0.f, m3 = 0.f;
        bool  s0 = false, s1 = false, s2 = false, s3 = false;
        uint32_t lo0 = 0, lo1 = 0, lo2 = 0, lo3 = 0;
        uint32_t hi0 = 0, hi1 = 0, hi2 = 0, hi3 = 0;

#pragma unroll
        for (int t = 0; t < T50; t++) {
            float t0 = __fadd_rn(__fmul_rn(BETA, m0), c0);
            float t1 = __fadd_rn(__fmul_rn(BETA, m1), c1);
            float t2 = __fadd_rn(__fmul_rn(BETA, m2), c2);
            float t3 = __fadd_rn(__fmul_rn(BETA, m3), c3);
            m0 = s0 ? __fadd_rn(t0, -1.0f) : t0;
            m1 = s1 ? __fadd_rn(t1, -1.0f) : t1;
            m2 = s2 ? __fadd_rn(t2, -1.0f) : t2;
            m3 = s3 ? __fadd_rn(t3, -1.0f) : t3;
            s0 = m0 > 1.0f; s1 = m1 > 1.0f; s2 = m2 > 1.0f; s3 = m3 > 1.0f;
            if (t < 32) {
                lo0 |= s0 ? (1u << t) : 0u; lo1 |= s1 ? (1u << t) : 0u;
                lo2 |= s2 ? (1u << t) : 0u; lo3 |= s3 ? (1u << t) : 0u;
            } else {
                hi0 |= s0 ? (1u << (t - 32)) : 0u; hi1 |= s1 ? (1u << (t - 32)) : 0u;
                hi2 |= s2 ? (1u << (t - 32)) : 0u; hi3 |= s3 ? (1u << (t - 32)) : 0u;
            }
        }

        // Pack each 2-col group as a contiguous 100-bit stream in 4 words:
        //  w0 = c0 bits 0..31 ; w1 = c0 bits 32..49 | c1 bits 0..13 << 18
        //  w2 = c1 bits 14..45 ; w3 = c1 bits 46..49
        const int r = (ty << 2) + i;
        {
            uint4 w;
            w.x = lo0;
            w.y = hi0 | (lo1 << 18);
            w.z = __funnelshift_r(lo1, hi1, 14);
            w.w = hi1 >> 14;
            *reinterpret_cast<uint4*>(&s_msk[((r << 4) + (tx << 1)) << 2]) = w;
            w.x = lo2;
            w.y = hi2 | (lo3 << 18);
            w.z = __funnelshift_r(lo3, hi3, 14);
            w.w = hi3 >> 14;
            *reinterpret_cast<uint4*>(&s_msk[((r << 4) + (tx << 1) + 1) << 2]) = w;
        }
    }
    __syncthreads();

    // ---------------- Expansion: nibble -> LUT -> STG.128 -------------------
    // Warp w owns rows [16w,16w+16). Per row: 16 groups x 25 float4.
    // Lane L covers stream bits [4L,4L+4): word = L>>3, shift = (4L)&31.
    const int lane = tid & 31;
    const int warp = tid >> 5;

    if (lane < 25) {
        const int word = lane >> 3;
        const int shft = (lane << 2) & 31;
#pragma unroll
        for (int rr = 0; rr < 16; rr++) {
            int row = (warp << 4) + rr;
            const uint32_t* mrow = s_msk + (row << 6);
            float4* gout = reinterpret_cast<float4*>(
                out + (size_t)(row0 + row) * ROW_ELEMS + (size_t)col0 * T50) + lane;
#pragma unroll 4
            for (int cc = 0; cc < 16; cc++) {
                uint32_t nib = (mrow[(cc << 2) + word] >> shft) & 0xFu;
                __stcs(&gout[cc * 25], lut4[nib]);
            }
        }
    }
}

extern "C" void kernel_launch(void* const* d_in, const int* in_sizes, int n_in,
                              void* d_out, int out_size)
{
    const float* x    = (const float*)d_in[0];   // [8192, 512]
    const float* W    = (const float*)d_in[1];   // [256, 512]
    const float* bias = (const float*)d_in[2];   // [256]
    float*       out  = (float*)d_out;           // [8192, 256, 50]

    dim3 grid(OUT_DIM / TILE_N, B_DIM / TILE_M); // (8, 128) = 1024 blocks
    snn_fused3<<<grid, 128>>>(x, W, bias, out);
}

// round 7
// speedup vs baseline: 1.6401x; 1.6401x over previous
#include <cuda_runtime.h>
#include <stdint.h>

#define BETA      0.99f
#define T50       50
#define B_DIM     8192
#define IN_DIM    512
#define OUT_DIM   256

#define TILE_M    64          // batch rows per block
#define TILE_N    32          // output cols per block
#define BK        16
#define ROW_ELEMS (OUT_DIM * T50)   // 12800 floats per batch row

__global__ __launch_bounds__(128, 6) void snn_fused4(
    const float* __restrict__ x,     // [B_DIM, IN_DIM]
    const float* __restrict__ W,     // [OUT_DIM, IN_DIM]
    const float* __restrict__ bias,  // [OUT_DIM]
    float* __restrict__ out)         // [B_DIM, OUT_DIM, T50]
{
    __shared__ float As[BK][68];                 // k-major, padded
    __shared__ float Bs[BK][36];
    __shared__ uint32_t s_msk[TILE_M * 16 * 4];  // 16 KB: [row][colpair][4 words, 100-bit stream]
    __shared__ float4 lut4[16];                  // nibble -> 4 spike floats

    const int tid  = threadIdx.x;
    const int tx   = tid & 7;           // col group (4 cols each -> 32)
    const int ty   = tid >> 3;          // row group (4 rows each -> 64)
    const int col0 = blockIdx.x * TILE_N;
    const int row0 = blockIdx.y * TILE_M;

    if (tid < 16)                       // synced by first barrier in GEMM loop
        lut4[tid] = make_float4((float)(tid & 1), (float)((tid >> 1) & 1),
                                (float)((tid >> 2) & 1), (float)((tid >> 3) & 1));

    // ---------------- GEMM: cur = x @ W^T + b  (k strictly ascending) -------
    // Identical instruction stream to the 127us round-5 kernel.
    float acc[16];
#pragma unroll
    for (int e = 0; e < 16; e++) acc[e] = 0.0f;

    const int lr = tid >> 2;            // 0..31
    const int lc = (tid & 3) << 2;      // 0,4,8,12
    const float* xp0 = x + (size_t)(row0 + lr) * IN_DIM + lc;
    const float* xp1 = xp0 + (size_t)32 * IN_DIM;
    const float* wp0 = W + (size_t)(col0 + lr) * IN_DIM + lc;

    float4 va0 = *reinterpret_cast<const float4*>(xp0);
    float4 va1 = *reinterpret_cast<const float4*>(xp1);
    float4 vb0 = *reinterpret_cast<const float4*>(wp0);

    for (int k0 = 0; k0 < IN_DIM; k0 += BK) {
        As[lc + 0][lr]      = va0.x; As[lc + 1][lr]      = va0.y;
        As[lc + 2][lr]      = va0.z; As[lc + 3][lr]      = va0.w;
        As[lc + 0][lr + 32] = va1.x; As[lc + 1][lr + 32] = va1.y;
        As[lc + 2][lr + 32] = va1.z; As[lc + 3][lr + 32] = va1.w;
        Bs[lc + 0][lr]      = vb0.x; Bs[lc + 1][lr]      = vb0.y;
        Bs[lc + 2][lr]      = vb0.z; Bs[lc + 3][lr]      = vb0.w;
        __syncthreads();

        if (k0 + BK < IN_DIM) {         // prefetch next chunk under the FFMAs
            va0 = *reinterpret_cast<const float4*>(xp0 + k0 + BK);
            va1 = *reinterpret_cast<const float4*>(xp1 + k0 + BK);
            vb0 = *reinterpret_cast<const float4*>(wp0 + k0 + BK);
        }

#pragma unroll
        for (int kk = 0; kk < BK; kk++) {
            float4 a = *reinterpret_cast<const float4*>(&As[kk][ty << 2]);
            float4 b = *reinterpret_cast<const float4*>(&Bs[kk][tx << 2]);
            float av[4] = {a.x, a.y, a.z, a.w};
            float bv[4] = {b.x, b.y, b.z, b.w};
#pragma unroll
            for (int i = 0; i < 4; i++)
#pragma unroll
                for (int j = 0; j < 4; j++)
                    acc[i * 4 + j] = fmaf(av[i], bv[j], acc[i * 4 + j]);
        }
        __syncthreads();
    }

    {   // bias add (plain fp32 add, as in all passing rounds)
        float4 b4 = *reinterpret_cast<const float4*>(&bias[col0 + (tx << 2)]);
        float bb[4] = {b4.x, b4.y, b4.z, b4.w};
#pragma unroll
        for (int i = 0; i < 4; i++)
#pragma unroll
            for (int j = 0; j < 4; j++)
                acc[i * 4 + j] = acc[i * 4 + j] + bb[j];
    }

    // ---------------- LIF recurrence (bit-exact) + packed mask write --------
#pragma unroll
    for (int i = 0; i < 4; i++) {
        float c0 = acc[i * 4 + 0], c1 = acc[i * 4 + 1];
        float c2 = acc[i * 4 + 2], c3 = acc[i * 4 + 3];
        float m0 = 0.f, m1 = 0.f, m2 = 0.f, m3 = 0.f;
        bool  s0 = false, s1 = false, s2 = false, s3 = false;
        uint32_t lo0 = 0, lo1 = 0, lo2 = 0, lo3 = 0;
        uint32_t hi0 = 0, hi1 = 0, hi2 = 0, hi3 = 0;

#pragma unroll
        for (int t = 0; t < T50; t++) {
            float t0 = __fadd_rn(__fmul_rn(BETA, m0), c0);
            float t1 = __fadd_rn(__fmul_rn(BETA, m1), c1);
            float t2 = __fadd_rn(__fmul_rn(BETA, m2), c2);
            float t3 = __fadd_rn(__fmul_rn(BETA, m3), c3);
            m0 = s0 ? __fadd_rn(t0, -1.0f) : t0;
            m1 = s1 ? __fadd_rn(t1, -1.0f) : t1;
            m2 = s2 ? __fadd_rn(t2, -1.0f) : t2;
            m3 = s3 ? __fadd_rn(t3, -1.0f) : t3;
            s0 = m0 > 1.0f; s1 = m1 > 1.0f; s2 = m2 > 1.0f; s3 = m3 > 1.0f;
            if (t < 32) {
                lo0 |= s0 ? (1u << t) : 0u; lo1 |= s1 ? (1u << t) : 0u;
                lo2 |= s2 ? (1u << t) : 0u; lo3 |= s3 ? (1u << t) : 0u;
            } else {
                hi0 |= s0 ? (1u << (t - 32)) : 0u; hi1 |= s1 ? (1u << (t - 32)) : 0u;
                hi2 |= s2 ? (1u << (t - 32)) : 0u; hi3 |= s3 ? (1u << (t - 32)) : 0u;
            }
        }

        // Pack each 2-col group as a contiguous 100-bit stream in 4 words:
        //  w0 = c0 bits 0..31 ; w1 = c0 bits 32..49 | c1 bits 0..13 << 18
        //  w2 = c1 bits 14..45 ; w3 = c1 bits 46..49    (verified in round 6)
        const int r = (ty << 2) + i;
        {
            uint4 w;
            w.x = lo0;
            w.y = hi0 | (lo1 << 18);
            w.z = __funnelshift_r(lo1, hi1, 14);
            w.w = hi1 >> 14;
            *reinterpret_cast<uint4*>(&s_msk[((r << 4) + (tx << 1)) << 2]) = w;
            w.x = lo2;
            w.y = hi2 | (lo3 << 18);
            w.z = __funnelshift_r(lo3, hi3, 14);
            w.w = hi3 >> 14;
            *reinterpret_cast<uint4*>(&s_msk[((r << 4) + (tx << 1) + 1) << 2]) = w;
        }
    }
    __syncthreads();

    // ---------------- Expansion: nibble -> LUT -> STG.128 -------------------
    // Warp w owns rows [16w,16w+16). Per row: 16 groups x 25 float4.
    // Lane L covers stream bits [4L,4L+4): word = L>>3, shift = (4L)&31.
    // Mask LDS.32 is a broadcast (8 lanes share each word); LUT LDS.128 is 1
    // issue slot regardless of conflict degree.
    const int lane = tid & 31;
    const int warp = tid >> 5;

    if (lane < 25) {
        const int word = lane >> 3;
        const int shft = (lane << 2) & 31;
#pragma unroll
        for (int rr = 0; rr < 16; rr++) {
            int row = (warp << 4) + rr;
            const uint32_t* mrow = s_msk + (row << 6);      // 16 groups * 4 words
            float4* gout = reinterpret_cast<float4*>(
                out + (size_t)(row0 + row) * ROW_ELEMS + (size_t)col0 * T50) + lane;
#pragma unroll 4
            for (int cc = 0; cc < 16; cc++) {
                uint32_t nib = (mrow[(cc << 2) + word] >> shft) & 0xFu;
                __stcs(&gout[cc * 25], lut4[nib]);
            }
        }
    }
}

extern "C" void kernel_launch(void* const* d_in, const int* in_sizes, int n_in,
                              void* d_out, int out_size)
{
    const float* x    = (const float*)d_in[0];   // [8192, 512]
    const float* W    = (const float*)d_in[1];   // [256, 512]
    const float* bias = (const float*)d_in[2];   // [256]
    float*       out  = (float*)d_out;           // [8192, 256, 50]

    dim3 grid(OUT_DIM / TILE_N, B_DIM / TILE_M); // (8, 128) = 1024 blocks
    snn_fused4<<<grid, 128>>>(x, W, bias, out);
}